// round 4
// baseline (speedup 1.0000x reference)
#include <cuda_runtime.h>
#include <math.h>

#define T_STEPS 4096
#define H_DIM   2048
#define O_DIM   512

#define RNN_CTAS    128
#define RNN_THREADS 256

// ---------------- device scratch (allocation-free rule) ----------------
__device__ float g_xp[(size_t)T_STEPS * H_DIM];   // x @ W_ih^T + b_ih + b_hh
__device__ float g_hs[(size_t)T_STEPS * H_DIM];   // all hidden states h_t
__device__ int   g_flags[RNN_CTAS];               // flag[c] = steps completed by CTA c

// strong (morally strong, gpu scope) ld/st for the flag protocol
__device__ __forceinline__ int ld_relaxed_gpu(const int* p)
{
    int v;
    asm volatile("ld.relaxed.gpu.global.b32 %0, [%1];" : "=r"(v) : "l"(p));
    return v;
}
__device__ __forceinline__ void st_relaxed_gpu(int* p, int v)
{
    asm volatile("st.relaxed.gpu.global.b32 [%0], %1;" :: "l"(p), "r"(v));
}

// ---------------- flag reset (graph-replay safe) -----------------------
__global__ void reset_flags_kernel()
{
    if (threadIdx.x < RNN_CTAS) g_flags[threadIdx.x] = 0;
}

// ---------------- persistent recurrence kernel -------------------------
// h_t = tanh(xp_t + W_hh @ h_{t-1}); W_hh rows live in registers.
// 128 CTAs x 16 rows. 8 warps/CTA, 2 rows/warp, 64 k-elems (16 float4)/lane.
// Compute path is bit-identical to the R1 passing kernel.
__global__ void __launch_bounds__(RNN_THREADS, 1)
rnn_kernel(const float* __restrict__ W_hh, const float* __restrict__ h0)
{
    __shared__ __align__(16) float hbuf[H_DIM];
    const int tid  = threadIdx.x;
    const int lane = tid & 31;
    const int wid  = tid >> 5;                    // 0..7
    const int r0   = blockIdx.x * 16 + wid * 2;   // this warp's two rows

    // Load this warp's two weight rows into registers.
    float4 w0[16], w1[16];
    const float4* W0 = (const float4*)(W_hh + (size_t)r0 * H_DIM);
    const float4* W1 = (const float4*)(W_hh + (size_t)(r0 + 1) * H_DIM);
#pragma unroll
    for (int j = 0; j < 16; j++) {
        w0[j] = __ldg(&W0[j * 32 + lane]);
        w1[j] = __ldg(&W1[j * 32 + lane]);
    }

    for (int t = 0; t < T_STEPS; t++) {
        // xp prefetch: independent of h_{t-1}
        float xpv0 = 0.f, xpv1 = 0.f;
        if (lane == 0) {
            xpv0 = __ldg(&g_xp[(size_t)t * H_DIM + r0]);
            xpv1 = __ldg(&g_xp[(size_t)t * H_DIM + r0 + 1]);
        }

        // Wait until every CTA has completed step t-1 (flags >= t).
        // All threads poll (4 distinct flag words per lane, strong relaxed
        // loads), then each thread acquire-fences before touching h.
        if (t > 0) {
            bool ready;
            do {
                int a = ld_relaxed_gpu(&g_flags[lane]);
                int b = ld_relaxed_gpu(&g_flags[lane + 32]);
                int c = ld_relaxed_gpu(&g_flags[lane + 64]);
                int d = ld_relaxed_gpu(&g_flags[lane + 96]);
                int m = min(min(a, b), min(c, d));
                ready = __all_sync(0xffffffffu, m >= t);
            } while (!ready);
            __threadfence();                   // acquire
        }

        const float4* hprev = (t == 0)
            ? (const float4*)h0
            : (const float4*)(g_hs + (size_t)(t - 1) * H_DIM);

        // Stage h_{t-1} into shared (L2 loads: written by other SMs).
        float4 a = __ldcg(&hprev[tid]);
        float4 b = __ldcg(&hprev[tid + RNN_THREADS]);
        ((float4*)hbuf)[tid]               = a;
        ((float4*)hbuf)[tid + RNN_THREADS] = b;
        __syncthreads();

        float acc0 = 0.f, acc1 = 0.f;
#pragma unroll
        for (int j = 0; j < 16; j++) {
            float4 h4 = ((const float4*)hbuf)[j * 32 + lane];  // conflict-free
            acc0 += w0[j].x * h4.x; acc1 += w1[j].x * h4.x;
            acc0 += w0[j].y * h4.y; acc1 += w1[j].y * h4.y;
            acc0 += w0[j].z * h4.z; acc1 += w1[j].z * h4.z;
            acc0 += w0[j].w * h4.w; acc1 += w1[j].w * h4.w;
        }

#pragma unroll
        for (int off = 16; off > 0; off >>= 1) {
            acc0 += __shfl_down_sync(0xffffffffu, acc0, off);
            acc1 += __shfl_down_sync(0xffffffffu, acc1, off);
        }

        // Publish h_t: each WRITER fences its own stores (this is the fix —
        // previously only tid0 fenced, leaving other warps' stores unordered
        // w.r.t. the arrival signal), then BAR, then one strong flag store.
        if (lane == 0) {
            g_hs[(size_t)t * H_DIM + r0]     = tanhf(xpv0 + acc0);
            g_hs[(size_t)t * H_DIM + r0 + 1] = tanhf(xpv1 + acc1);
            __threadfence();                   // release (writer-side)
        }
        __syncthreads();
        if (tid == 0) {
            st_relaxed_gpu(&g_flags[blockIdx.x], t + 1);
        }
    }
}

// ---------------- tiled fp32 NT GEMM: C[M,N] = A[M,K] @ B[N,K]^T + bias --
// PHASE 0: A = param (x),   C = g_xp,  bias = b_ih + b_hh
// PHASE 1: A = g_hs,        C = param, bias = b_lin
#define BM 128
#define BN 64
#define BK 16

template<int PHASE>
__global__ void __launch_bounds__(256, 2)
gemm_nt_bias(const float* __restrict__ A_param,
             const float* __restrict__ B,
             const float* __restrict__ bias1,
             const float* __restrict__ bias2,
             float* __restrict__ C_param,
             int M, int N, int K)
{
    __shared__ __align__(16) float As[BK][BM + 4];
    __shared__ __align__(16) float Bs[BK][BN + 4];

    const float* A = (PHASE == 0) ? A_param : g_hs;
    float*       C = (PHASE == 0) ? g_xp    : C_param;

    const int tid = threadIdx.x;
    const int m0  = blockIdx.y * BM;
    const int n0  = blockIdx.x * BN;
    const int ty  = tid >> 4;    // 0..15 -> rows ty*8..+7
    const int tx  = tid & 15;    // 0..15 -> cols tx*4..+3

    float acc[8][4];
#pragma unroll
    for (int i = 0; i < 8; i++)
#pragma unroll
        for (int j = 0; j < 4; j++) acc[i][j] = 0.f;

    for (int k0 = 0; k0 < K; k0 += BK) {
        // A tile: 128x16 = 512 float4, 2 per thread
#pragma unroll
        for (int it = 0; it < 2; it++) {
            int idx = tid + it * 256;
            int row = idx >> 2, kq = idx & 3;
            float4 v = *(const float4*)(A + (size_t)(m0 + row) * K + k0 + kq * 4);
            As[kq * 4 + 0][row] = v.x;
            As[kq * 4 + 1][row] = v.y;
            As[kq * 4 + 2][row] = v.z;
            As[kq * 4 + 3][row] = v.w;
        }
        // B tile: 64x16 = 256 float4, 1 per thread
        {
            int row = tid >> 2, kq = tid & 3;
            float4 v = *(const float4*)(B + (size_t)(n0 + row) * K + k0 + kq * 4);
            Bs[kq * 4 + 0][row] = v.x;
            Bs[kq * 4 + 1][row] = v.y;
            Bs[kq * 4 + 2][row] = v.z;
            Bs[kq * 4 + 3][row] = v.w;
        }
        __syncthreads();

#pragma unroll
        for (int kk = 0; kk < BK; kk++) {
            float4 a0 = *(const float4*)&As[kk][ty * 8];
            float4 a1 = *(const float4*)&As[kk][ty * 8 + 4];
            float4 bv = *(const float4*)&Bs[kk][tx * 4];
            float av[8] = {a0.x, a0.y, a0.z, a0.w, a1.x, a1.y, a1.z, a1.w};
            float bb[4] = {bv.x, bv.y, bv.z, bv.w};
#pragma unroll
            for (int i = 0; i < 8; i++)
#pragma unroll
                for (int j = 0; j < 4; j++)
                    acc[i][j] += av[i] * bb[j];
        }
        __syncthreads();
    }

    // epilogue: bias + store
    float bsum[4];
#pragma unroll
    for (int j = 0; j < 4; j++) {
        int n = n0 + tx * 4 + j;
        float bv = __ldg(&bias1[n]);
        if (bias2) bv += __ldg(&bias2[n]);
        bsum[j] = bv;
    }
#pragma unroll
    for (int i = 0; i < 8; i++) {
        float4 o;
        o.x = acc[i][0] + bsum[0];
        o.y = acc[i][1] + bsum[1];
        o.z = acc[i][2] + bsum[2];
        o.w = acc[i][3] + bsum[3];
        *(float4*)(C + (size_t)(m0 + ty * 8 + i) * N + n0 + tx * 4) = o;
    }
}

// ---------------- launch ------------------------------------------------
extern "C" void kernel_launch(void* const* d_in, const int* in_sizes, int n_in,
                              void* d_out, int out_size)
{
    const float* x     = (const float*)d_in[0];  // (T,1,H)
    const float* W_ih  = (const float*)d_in[1];  // (H,H)
    const float* W_hh  = (const float*)d_in[2];  // (H,H)
    const float* b_ih  = (const float*)d_in[3];  // (H)
    const float* b_hh  = (const float*)d_in[4];  // (H)
    const float* W_lin = (const float*)d_in[5];  // (O,H)
    const float* b_lin = (const float*)d_in[6];  // (O)
    const float* h0    = (const float*)d_in[7];  // (1,1,H)
    float* out = (float*)d_out;                  // (T,1,O)

    // Reset per-CTA flags (must precede rnn_kernel every launch/replay).
    reset_flags_kernel<<<1, 128>>>();

    // Phase 1: g_xp = x @ W_ih^T + b_ih + b_hh
    gemm_nt_bias<0><<<dim3(H_DIM / BN, T_STEPS / BM), 256>>>(
        x, W_ih, b_ih, b_hh, nullptr, T_STEPS, H_DIM, H_DIM);

    // Phase 2: sequential recurrence -> g_hs
    rnn_kernel<<<RNN_CTAS, RNN_THREADS>>>(W_hh, h0);

    // Phase 3: out = g_hs @ W_lin^T + b_lin
    gemm_nt_bias<1><<<dim3(O_DIM / BN, T_STEPS / BM), 256>>>(
        nullptr, W_lin, b_lin, nullptr, out, T_STEPS, O_DIM, H_DIM);
}

// round 6
// speedup vs baseline: 1.5739x; 1.5739x over previous
#include <cuda_runtime.h>
#include <math.h>

#define T_STEPS 4096
#define H_DIM   2048
#define O_DIM   512

#define RNN_CTAS    128
#define RNN_THREADS 256

// ---------------- device scratch (allocation-free rule) ----------------
__device__ float g_xp[(size_t)T_STEPS * H_DIM];   // x @ W_ih^T + b_ih + b_hh
__device__ float g_hs[(size_t)T_STEPS * H_DIM];   // all hidden states h_t
__device__ int   g_flags[RNN_CTAS];               // flag[c] = steps completed by CTA c

// strong (morally strong, gpu scope) ld/st for the flag protocol
__device__ __forceinline__ int ld_relaxed_gpu(const int* p)
{
    int v;
    asm volatile("ld.relaxed.gpu.global.b32 %0, [%1];" : "=r"(v) : "l"(p));
    return v;
}
__device__ __forceinline__ void st_relaxed_gpu(int* p, int v)
{
    asm volatile("st.relaxed.gpu.global.b32 [%0], %1;" :: "l"(p), "r"(v));
}

// ---------------- flag reset (graph-replay safe) -----------------------
__global__ void reset_flags_kernel()
{
    if (threadIdx.x < RNN_CTAS) g_flags[threadIdx.x] = 0;
}

// ---------------- persistent recurrence kernel -------------------------
// h_t = tanh(xp_t + W_hh @ h_{t-1}); W_hh rows live in registers.
// 128 CTAs x 16 rows. 8 warps/CTA, 2 rows/warp, 64 k-elems (16 float4)/lane.
// Compute path is bit-identical to the R1/R4 passing kernels.
// Sync: R4's proven protocol, but ONLY WARP 0 polls (R4's all-thread
// polling queued thousands of strong loads on 4 LTS slices).
__global__ void __launch_bounds__(RNN_THREADS, 1)
rnn_kernel(const float* __restrict__ W_hh, const float* __restrict__ h0)
{
    __shared__ __align__(16) float hbuf[H_DIM];
    const int tid  = threadIdx.x;
    const int lane = tid & 31;
    const int wid  = tid >> 5;                    // 0..7
    const int r0   = blockIdx.x * 16 + wid * 2;   // this warp's two rows

    // Load this warp's two weight rows into registers.
    float4 w0[16], w1[16];
    const float4* W0 = (const float4*)(W_hh + (size_t)r0 * H_DIM);
    const float4* W1 = (const float4*)(W_hh + (size_t)(r0 + 1) * H_DIM);
#pragma unroll
    for (int j = 0; j < 16; j++) {
        w0[j] = __ldg(&W0[j * 32 + lane]);
        w1[j] = __ldg(&W1[j * 32 + lane]);
    }

    for (int t = 0; t < T_STEPS; t++) {
        // xp prefetch: independent of h_{t-1}
        float xpv0 = 0.f, xpv1 = 0.f;
        if (lane == 0) {
            xpv0 = __ldg(&g_xp[(size_t)t * H_DIM + r0]);
            xpv1 = __ldg(&g_xp[(size_t)t * H_DIM + r0 + 1]);
        }

        // Wait until every CTA has completed step t-1 (flags >= t).
        // ONLY warp 0 polls: each of its 4 loads covers one full 128B line
        // (lane l -> flags[l + 32k]), so one poll iteration = 4 coalesced
        // line requests per CTA instead of R4's per-thread storm.
        if (t > 0) {
            if (wid == 0) {
                bool ready;
                do {
                    int a = ld_relaxed_gpu(&g_flags[lane]);
                    int b = ld_relaxed_gpu(&g_flags[lane + 32]);
                    int c = ld_relaxed_gpu(&g_flags[lane + 64]);
                    int d = ld_relaxed_gpu(&g_flags[lane + 96]);
                    int m = min(min(a, b), min(c, d));
                    ready = __all_sync(0xffffffffu, m >= t);
                } while (!ready);
                __threadfence();               // acquire (warp 0)
            }
            __syncthreads();                   // propagate via bar causality
        }

        const float4* hprev = (t == 0)
            ? (const float4*)h0
            : (const float4*)(g_hs + (size_t)(t - 1) * H_DIM);

        // Stage h_{t-1} into shared (L2 loads: written by other SMs).
        float4 a = __ldcg(&hprev[tid]);
        float4 b = __ldcg(&hprev[tid + RNN_THREADS]);
        ((float4*)hbuf)[tid]               = a;
        ((float4*)hbuf)[tid + RNN_THREADS] = b;
        __syncthreads();

        float acc0 = 0.f, acc1 = 0.f;
#pragma unroll
        for (int j = 0; j < 16; j++) {
            float4 h4 = ((const float4*)hbuf)[j * 32 + lane];  // conflict-free
            acc0 += w0[j].x * h4.x; acc1 += w1[j].x * h4.x;
            acc0 += w0[j].y * h4.y; acc1 += w1[j].y * h4.y;
            acc0 += w0[j].z * h4.z; acc1 += w1[j].z * h4.z;
            acc0 += w0[j].w * h4.w; acc1 += w1[j].w * h4.w;
        }

#pragma unroll
        for (int off = 16; off > 0; off >>= 1) {
            acc0 += __shfl_down_sync(0xffffffffu, acc0, off);
            acc1 += __shfl_down_sync(0xffffffffu, acc1, off);
        }

        // Publish h_t: each WRITER fences its own stores, then BAR, then one
        // strong per-CTA flag store (no atomics -> no same-address serialization).
        if (lane == 0) {
            g_hs[(size_t)t * H_DIM + r0]     = tanhf(xpv0 + acc0);
            g_hs[(size_t)t * H_DIM + r0 + 1] = tanhf(xpv1 + acc1);
            __threadfence();                   // release (writer-side)
        }
        __syncthreads();
        if (tid == 0) {
            st_relaxed_gpu(&g_flags[blockIdx.x], t + 1);
        }
    }
}

// ---------------- tiled fp32 NT GEMM: C[M,N] = A[M,K] @ B[N,K]^T + bias --
// PHASE 0: A = param (x),   C = g_xp,  bias = b_ih + b_hh
// PHASE 1: A = g_hs,        C = param, bias = b_lin
#define BM 128
#define BN 64
#define BK 16

template<int PHASE>
__global__ void __launch_bounds__(256, 2)
gemm_nt_bias(const float* __restrict__ A_param,
             const float* __restrict__ B,
             const float* __restrict__ bias1,
             const float* __restrict__ bias2,
             float* __restrict__ C_param,
             int M, int N, int K)
{
    __shared__ __align__(16) float As[BK][BM + 4];
    __shared__ __align__(16) float Bs[BK][BN + 4];

    const float* A = (PHASE == 0) ? A_param : g_hs;
    float*       C = (PHASE == 0) ? g_xp    : C_param;

    const int tid = threadIdx.x;
    const int m0  = blockIdx.y * BM;
    const int n0  = blockIdx.x * BN;
    const int ty  = tid >> 4;    // 0..15 -> rows ty*8..+7
    const int tx  = tid & 15;    // 0..15 -> cols tx*4..+3

    float acc[8][4];
#pragma unroll
    for (int i = 0; i < 8; i++)
#pragma unroll
        for (int j = 0; j < 4; j++) acc[i][j] = 0.f;

    for (int k0 = 0; k0 < K; k0 += BK) {
        // A tile: 128x16 = 512 float4, 2 per thread
#pragma unroll
        for (int it = 0; it < 2; it++) {
            int idx = tid + it * 256;
            int row = idx >> 2, kq = idx & 3;
            float4 v = *(const float4*)(A + (size_t)(m0 + row) * K + k0 + kq * 4);
            As[kq * 4 + 0][row] = v.x;
            As[kq * 4 + 1][row] = v.y;
            As[kq * 4 + 2][row] = v.z;
            As[kq * 4 + 3][row] = v.w;
        }
        // B tile: 64x16 = 256 float4, 1 per thread
        {
            int row = tid >> 2, kq = tid & 3;
            float4 v = *(const float4*)(B + (size_t)(n0 + row) * K + k0 + kq * 4);
            Bs[kq * 4 + 0][row] = v.x;
            Bs[kq * 4 + 1][row] = v.y;
            Bs[kq * 4 + 2][row] = v.z;
            Bs[kq * 4 + 3][row] = v.w;
        }
        __syncthreads();

#pragma unroll
        for (int kk = 0; kk < BK; kk++) {
            float4 a0 = *(const float4*)&As[kk][ty * 8];
            float4 a1 = *(const float4*)&As[kk][ty * 8 + 4];
            float4 bv = *(const float4*)&Bs[kk][tx * 4];
            float av[8] = {a0.x, a0.y, a0.z, a0.w, a1.x, a1.y, a1.z, a1.w};
            float bb[4] = {bv.x, bv.y, bv.z, bv.w};
#pragma unroll
            for (int i = 0; i < 8; i++)
#pragma unroll
                for (int j = 0; j < 4; j++)
                    acc[i][j] += av[i] * bb[j];
        }
        __syncthreads();
    }

    // epilogue: bias + store
    float bsum[4];
#pragma unroll
    for (int j = 0; j < 4; j++) {
        int n = n0 + tx * 4 + j;
        float bv = __ldg(&bias1[n]);
        if (bias2) bv += __ldg(&bias2[n]);
        bsum[j] = bv;
    }
#pragma unroll
    for (int i = 0; i < 8; i++) {
        float4 o;
        o.x = acc[i][0] + bsum[0];
        o.y = acc[i][1] + bsum[1];
        o.z = acc[i][2] + bsum[2];
        o.w = acc[i][3] + bsum[3];
        *(float4*)(C + (size_t)(m0 + ty * 8 + i) * N + n0 + tx * 4) = o;
    }
}

// ---------------- launch ------------------------------------------------
extern "C" void kernel_launch(void* const* d_in, const int* in_sizes, int n_in,
                              void* d_out, int out_size)
{
    const float* x     = (const float*)d_in[0];  // (T,1,H)
    const float* W_ih  = (const float*)d_in[1];  // (H,H)
    const float* W_hh  = (const float*)d_in[2];  // (H,H)
    const float* b_ih  = (const float*)d_in[3];  // (H)
    const float* b_hh  = (const float*)d_in[4];  // (H)
    const float* W_lin = (const float*)d_in[5];  // (O,H)
    const float* b_lin = (const float*)d_in[6];  // (O)
    const float* h0    = (const float*)d_in[7];  // (1,1,H)
    float* out = (float*)d_out;                  // (T,1,O)

    // Reset per-CTA flags (must precede rnn_kernel every launch/replay).
    reset_flags_kernel<<<1, 128>>>();

    // Phase 1: g_xp = x @ W_ih^T + b_ih + b_hh
    gemm_nt_bias<0><<<dim3(H_DIM / BN, T_STEPS / BM), 256>>>(
        x, W_ih, b_ih, b_hh, nullptr, T_STEPS, H_DIM, H_DIM);

    // Phase 2: sequential recurrence -> g_hs
    rnn_kernel<<<RNN_CTAS, RNN_THREADS>>>(W_hh, h0);

    // Phase 3: out = g_hs @ W_lin^T + b_lin
    gemm_nt_bias<1><<<dim3(O_DIM / BN, T_STEPS / BM), 256>>>(
        nullptr, W_lin, b_lin, nullptr, out, T_STEPS, O_DIM, H_DIM);
}

// round 8
// speedup vs baseline: 4.2275x; 2.6860x over previous
#include <cuda_runtime.h>
#include <math.h>

#define T_STEPS 4096
#define H_DIM   2048
#define O_DIM   512

#define RNN_CTAS    128
#define RNN_THREADS 256

#define SENTINEL 0x7f800001u   // NaN payload; tanh(finite) can never produce it

// ---------------- device scratch (allocation-free rule) ----------------
__device__ float g_xp[(size_t)T_STEPS * H_DIM];   // x @ W_ih^T + b_ih + b_hh
__device__ float g_hs[(size_t)T_STEPS * H_DIM];   // all hidden states h_t

// Morally-strong volatile ops for the data-as-flag protocol.
// "memory" clobbers pin compiler ordering; volatile pins HW ordering.
__device__ __forceinline__ uint4 ld_vol_u4(const uint4* p)
{
    uint4 v;
    asm volatile("ld.volatile.global.v4.u32 {%0,%1,%2,%3}, [%4];"
                 : "=r"(v.x), "=r"(v.y), "=r"(v.z), "=r"(v.w)
                 : "l"(p) : "memory");
    return v;
}
__device__ __forceinline__ void st_vol_f32(float* p, float v)
{
    asm volatile("st.volatile.global.f32 [%0], %1;"
                 :: "l"(p), "f"(v) : "memory");
}

__device__ __forceinline__ bool has_sent(uint4 v)
{
    return (v.x == SENTINEL) | (v.y == SENTINEL) |
           (v.z == SENTINEL) | (v.w == SENTINEL);
}

// ---------------- sentinel reset (graph-replay safe) -------------------
// 8M floats = 2M uint4; grid 8192 x 256.
__global__ void reset_hs_kernel()
{
    size_t i = (size_t)blockIdx.x * blockDim.x + threadIdx.x;
    ((uint4*)g_hs)[i] = make_uint4(SENTINEL, SENTINEL, SENTINEL, SENTINEL);
}

// ---------------- persistent recurrence kernel -------------------------
// h_t = tanh(xp_t + W_hh @ h_{t-1}); W_hh rows live in registers.
// 128 CTAs x 16 rows. 8 warps/CTA, 2 rows/warp, 64 k-elems (16 float4)/lane.
// Sync: data-as-flag. Consumers spin on the actual h words (sentinel-
// initialized) with VOLATILE loads; producers publish with VOLATILE stores.
// Morally-strong per-word atomicity replaces all fences/flags.
// Compute path is bit-identical to the R1/R4/R6 passing kernels.
__global__ void __launch_bounds__(RNN_THREADS, 1)
rnn_kernel(const float* __restrict__ W_hh, const float* __restrict__ h0)
{
    __shared__ __align__(16) float hbuf[H_DIM];
    const int tid  = threadIdx.x;
    const int lane = tid & 31;
    const int wid  = tid >> 5;                    // 0..7
    const int r0   = blockIdx.x * 16 + wid * 2;   // this warp's two rows

    // Load this warp's two weight rows into registers.
    float4 w0[16], w1[16];
    const float4* W0 = (const float4*)(W_hh + (size_t)r0 * H_DIM);
    const float4* W1 = (const float4*)(W_hh + (size_t)(r0 + 1) * H_DIM);
#pragma unroll
    for (int j = 0; j < 16; j++) {
        w0[j] = __ldg(&W0[j * 32 + lane]);
        w1[j] = __ldg(&W1[j * 32 + lane]);
    }

    for (int t = 0; t < T_STEPS; t++) {
        // xp prefetch: independent of h_{t-1}
        float xpv0 = 0.f, xpv1 = 0.f;
        if (lane == 0) {
            xpv0 = __ldg(&g_xp[(size_t)t * H_DIM + r0]);
            xpv1 = __ldg(&g_xp[(size_t)t * H_DIM + r0 + 1]);
        }

        // Acquire h_{t-1}: each thread spins on its own two 16B chunks until
        // sentinel-free. The poll IS the staging load — no flags, no fences.
        float4 a4, b4;
        if (t == 0) {
            a4 = __ldg(&((const float4*)h0)[tid]);
            b4 = __ldg(&((const float4*)h0)[tid + RNN_THREADS]);
        } else {
            const uint4* hp = (const uint4*)(g_hs + (size_t)(t - 1) * H_DIM);
            uint4 ua, ub;
            do { ua = ld_vol_u4(hp + tid); } while (has_sent(ua));
            do { ub = ld_vol_u4(hp + tid + RNN_THREADS); } while (has_sent(ub));
            a4 = make_float4(__uint_as_float(ua.x), __uint_as_float(ua.y),
                             __uint_as_float(ua.z), __uint_as_float(ua.w));
            b4 = make_float4(__uint_as_float(ub.x), __uint_as_float(ub.y),
                             __uint_as_float(ub.z), __uint_as_float(ub.w));
        }

        __syncthreads();   // previous iteration's LDS reads of hbuf are done
        ((float4*)hbuf)[tid]               = a4;
        ((float4*)hbuf)[tid + RNN_THREADS] = b4;
        __syncthreads();   // staging visible

        float acc0 = 0.f, acc1 = 0.f;
#pragma unroll
        for (int j = 0; j < 16; j++) {
            float4 h4 = ((const float4*)hbuf)[j * 32 + lane];  // conflict-free
            acc0 += w0[j].x * h4.x; acc1 += w1[j].x * h4.x;
            acc0 += w0[j].y * h4.y; acc1 += w1[j].y * h4.y;
            acc0 += w0[j].z * h4.z; acc1 += w1[j].z * h4.z;
            acc0 += w0[j].w * h4.w; acc1 += w1[j].w * h4.w;
        }

#pragma unroll
        for (int off = 16; off > 0; off >>= 1) {
            acc0 += __shfl_down_sync(0xffffffffu, acc0, off);
            acc1 += __shfl_down_sync(0xffffffffu, acc1, off);
        }

        // Publish h_t: volatile word stores, self-announcing.
        if (lane == 0) {
            st_vol_f32(&g_hs[(size_t)t * H_DIM + r0],     tanhf(xpv0 + acc0));
            st_vol_f32(&g_hs[(size_t)t * H_DIM + r0 + 1], tanhf(xpv1 + acc1));
        }
    }
}

// ---------------- tiled fp32 NT GEMM: C[M,N] = A[M,K] @ B[N,K]^T + bias --
// PHASE 0: A = param (x),   C = g_xp,  bias = b_ih + b_hh
// PHASE 1: A = g_hs,        C = param, bias = b_lin
#define BM 128
#define BN 64
#define BK 16

template<int PHASE>
__global__ void __launch_bounds__(256, 2)
gemm_nt_bias(const float* __restrict__ A_param,
             const float* __restrict__ B,
             const float* __restrict__ bias1,
             const float* __restrict__ bias2,
             float* __restrict__ C_param,
             int M, int N, int K)
{
    __shared__ __align__(16) float As[BK][BM + 4];
    __shared__ __align__(16) float Bs[BK][BN + 4];

    const float* A = (PHASE == 0) ? A_param : g_hs;
    float*       C = (PHASE == 0) ? g_xp    : C_param;

    const int tid = threadIdx.x;
    const int m0  = blockIdx.y * BM;
    const int n0  = blockIdx.x * BN;
    const int ty  = tid >> 4;    // 0..15 -> rows ty*8..+7
    const int tx  = tid & 15;    // 0..15 -> cols tx*4..+3

    float acc[8][4];
#pragma unroll
    for (int i = 0; i < 8; i++)
#pragma unroll
        for (int j = 0; j < 4; j++) acc[i][j] = 0.f;

    for (int k0 = 0; k0 < K; k0 += BK) {
        // A tile: 128x16 = 512 float4, 2 per thread
#pragma unroll
        for (int it = 0; it < 2; it++) {
            int idx = tid + it * 256;
            int row = idx >> 2, kq = idx & 3;
            float4 v = *(const float4*)(A + (size_t)(m0 + row) * K + k0 + kq * 4);
            As[kq * 4 + 0][row] = v.x;
            As[kq * 4 + 1][row] = v.y;
            As[kq * 4 + 2][row] = v.z;
            As[kq * 4 + 3][row] = v.w;
        }
        // B tile: 64x16 = 256 float4, 1 per thread
        {
            int row = tid >> 2, kq = tid & 3;
            float4 v = *(const float4*)(B + (size_t)(n0 + row) * K + k0 + kq * 4);
            Bs[kq * 4 + 0][row] = v.x;
            Bs[kq * 4 + 1][row] = v.y;
            Bs[kq * 4 + 2][row] = v.z;
            Bs[kq * 4 + 3][row] = v.w;
        }
        __syncthreads();

#pragma unroll
        for (int kk = 0; kk < BK; kk++) {
            float4 a0 = *(const float4*)&As[kk][ty * 8];
            float4 a1 = *(const float4*)&As[kk][ty * 8 + 4];
            float4 bv = *(const float4*)&Bs[kk][tx * 4];
            float av[8] = {a0.x, a0.y, a0.z, a0.w, a1.x, a1.y, a1.z, a1.w};
            float bb[4] = {bv.x, bv.y, bv.z, bv.w};
#pragma unroll
            for (int i = 0; i < 8; i++)
#pragma unroll
                for (int j = 0; j < 4; j++)
                    acc[i][j] += av[i] * bb[j];
        }
        __syncthreads();
    }

    // epilogue: bias + store
    float bsum[4];
#pragma unroll
    for (int j = 0; j < 4; j++) {
        int n = n0 + tx * 4 + j;
        float bv = __ldg(&bias1[n]);
        if (bias2) bv += __ldg(&bias2[n]);
        bsum[j] = bv;
    }
#pragma unroll
    for (int i = 0; i < 8; i++) {
        float4 o;
        o.x = acc[i][0] + bsum[0];
        o.y = acc[i][1] + bsum[1];
        o.z = acc[i][2] + bsum[2];
        o.w = acc[i][3] + bsum[3];
        *(float4*)(C + (size_t)(m0 + ty * 8 + i) * N + n0 + tx * 4) = o;
    }
}

// ---------------- launch ------------------------------------------------
extern "C" void kernel_launch(void* const* d_in, const int* in_sizes, int n_in,
                              void* d_out, int out_size)
{
    const float* x     = (const float*)d_in[0];  // (T,1,H)
    const float* W_ih  = (const float*)d_in[1];  // (H,H)
    const float* W_hh  = (const float*)d_in[2];  // (H,H)
    const float* b_ih  = (const float*)d_in[3];  // (H)
    const float* b_hh  = (const float*)d_in[4];  // (H)
    const float* W_lin = (const float*)d_in[5];  // (O,H)
    const float* b_lin = (const float*)d_in[6];  // (O)
    const float* h0    = (const float*)d_in[7];  // (1,1,H)
    float* out = (float*)d_out;                  // (T,1,O)

    // Reset g_hs to sentinel (must precede rnn_kernel every launch/replay).
    reset_hs_kernel<<<(T_STEPS * H_DIM / 4) / 256, 256>>>();

    // Phase 1: g_xp = x @ W_ih^T + b_ih + b_hh
    gemm_nt_bias<0><<<dim3(H_DIM / BN, T_STEPS / BM), 256>>>(
        x, W_ih, b_ih, b_hh, nullptr, T_STEPS, H_DIM, H_DIM);

    // Phase 2: sequential recurrence -> g_hs
    rnn_kernel<<<RNN_CTAS, RNN_THREADS>>>(W_hh, h0);

    // Phase 3: out = g_hs @ W_lin^T + b_lin
    gemm_nt_bias<1><<<dim3(O_DIM / BN, T_STEPS / BM), 256>>>(
        nullptr, W_lin, b_lin, nullptr, out, T_STEPS, O_DIM, H_DIM);
}